// round 9
// baseline (speedup 1.0000x reference)
#include <cuda_runtime.h>
#include <cuda_fp16.h>
#include <cstdint>

// Problem constants (fixed by the reference)
#define CIN   64
#define COUT  64
#define KOFF  27
#define MPAIR 131072
#define NOUT  262144
#define NIN   262144
#define EPS   1e-5f
#define SLOPE 0.01f

// Bucketing: 16 output ranges (out >> 14) x 27 k-offsets
#define NBKT_R      16
#define RANGE_SHIFT 14
#define NBUCKET     (NBKT_R * KOFF)      // 432
#define BKT_CAP     9216                 // slots/bucket = 18 blocks x 512
#define BLK_PER_BKT 18

// smem layout for conv kernel (dynamic):
//   [0, 8704)   : WsP — per-lane fp16x2 W blocks, 32 lanes x 68 uints
//   [8704, ..)  : buf0, buf1 — 2 x (128 staging rows x 68 floats)
#define WSP_STRIDE 68                    // uints per lane (64 + 4 pad)
#define WSP_BYTES  (32 * WSP_STRIDE * 4) // 8704
#define BUF_STRIDE 68                    // floats; 272B row stride, 16B mult
#define BUF_BYTES  (128 * BUF_STRIDE * 4)
#define SMEM_BYTES (WSP_BYTES + 2 * BUF_BYTES)

#define BIN_SMEM   (2 * 8192 * 4)        // staging for bin_kernel

// Pre-converted fp16 operands (device scratch; no runtime allocation)
// feats row layout (32 uints = 64 fp16): uint index p = a*8 + kk*2 + h
// holds half2( feats[ci], feats[ci+1] ), ci = kk*16 + 2a + 8h.
__device__ uint32_t g_featsH[NIN * 32];          // 33.5 MB
// W layout per k: 32 lanes x 64 uints; lane (r,a), uint kk*16 + j*2 + h
// holds half2( W[ci][co], W[ci+1][co] ), ci = kk*16+2a+8h, co = j*8+r.
__device__ uint32_t g_WH[KOFF * 2048];           // 216 KB

// Bucketed pair lists
__device__ int g_cursor[NBUCKET];                // alloc cursors / end ptrs
__device__ int g_im_s[NBUCKET * BKT_CAP];        // 15.9 MB
__device__ int g_om_s[NBUCKET * BKT_CAP];        // 15.9 MB

// BN statistics scratch
__device__ float g_sum[COUT];
__device__ float g_sumsq[COUT];

__device__ __forceinline__ uint32_t smem_u32(const void* p) {
    uint32_t a;
    asm("{ .reg .u64 t; cvta.to.shared.u64 t, %1; cvt.u32.u64 %0, t; }"
        : "=r"(a) : "l"(p));
    return a;
}

// ---------------------------------------------------------------------------
// Kernel 0: fused zero(out) + pre-convert feats/W to fp16 fragment layouts
//           + init bucket cursors.
// grid = 8192 x 256.
// ---------------------------------------------------------------------------
__global__ void __launch_bounds__(256)
precvt_kernel(const float* __restrict__ feats, const float* __restrict__ W,
              float4* __restrict__ out4)
{
    const int tid = threadIdx.x;
    const int t4  = blockIdx.x * 256 + tid;        // 0 .. 2,097,151

    // zero the 67 MB accumulator (2 float4s per thread)
    const float4 z = make_float4(0.f, 0.f, 0.f, 0.f);
    out4[2 * (size_t)t4]     = z;
    out4[2 * (size_t)t4 + 1] = z;
    if (blockIdx.x == 0 && tid < COUT) {
        g_sum[tid]   = 0.f;
        g_sumsq[tid] = 0.f;
    }
    if (blockIdx.x == 27) {
        for (int i = tid; i < NBUCKET; i += 256)
            g_cursor[i] = i * BKT_CAP;
    }

    const int row = t4 >> 3;
    const int p0  = (t4 & 7) << 2;                 // first of 4 uint slots

    const float* src = feats + (size_t)row * CIN;
    uint32_t v[4];
    #pragma unroll
    for (int i = 0; i < 4; i++) {
        const int up = p0 + i;
        const int a  = up >> 3;
        const int kk = (up >> 1) & 3;
        const int h  = up & 1;
        const int ci = kk * 16 + 2 * a + 8 * h;
        __half2 hv = __floats2half2_rn(src[ci], src[ci + 1]);
        v[i] = *reinterpret_cast<uint32_t*>(&hv);
    }
    *reinterpret_cast<uint4*>(g_featsH + (size_t)row * 32 + p0) =
        make_uint4(v[0], v[1], v[2], v[3]);

    if (blockIdx.x < KOFF) {
        const float* Wk = W + blockIdx.x * (CIN * COUT);
        uint32_t* dst = g_WH + blockIdx.x * 2048;
        for (int i = tid; i < 2048; i += 256) {
            // decode: i = lane*64 + kk*16 + j*2 + h ; lane = r*4 + a
            const int lane = i >> 6;
            const int rem  = i & 63;
            const int kk   = rem >> 4;
            const int j    = (rem >> 1) & 7;
            const int h    = rem & 1;
            const int r    = lane >> 2;
            const int a    = lane & 3;
            const int ci   = kk * 16 + 2 * a + 8 * h;
            const int co   = j * 8 + r;
            __half2 hv = __floats2half2_rn(Wk[ci * COUT + co],
                                           Wk[(ci + 1) * COUT + co]);
            dst[i] = *reinterpret_cast<uint32_t*>(&hv);
        }
    }
}

// ---------------------------------------------------------------------------
// Kernel 0c: counting-sort pairs into (out-range, k) buckets.
// grid = (16, 27); block handles 8192 consecutive pairs of its k.
// smem-staged so global writes are coalesced chunk copies.
// ---------------------------------------------------------------------------
__global__ void __launch_bounds__(256)
bin_kernel(const int* __restrict__ in_map, const int* __restrict__ out_map)
{
    __shared__ int hist[NBKT_R], lofs[NBKT_R + 1], gofs[NBKT_R], wcur[NBKT_R];
    extern __shared__ int stage[];          // [8192 im][8192 om]
    int* stage_im = stage;
    int* stage_om = stage + 8192;

    const int k   = blockIdx.y;
    const int off = blockIdx.x * 8192;
    const int* im = in_map  + k * MPAIR + off;
    const int* om = out_map + k * MPAIR + off;
    const int tid = threadIdx.x;

    if (tid < NBKT_R) hist[tid] = 0;
    __syncthreads();

    for (int i = tid; i < 8192; i += 256)
        atomicAdd(&hist[om[i] >> RANGE_SHIFT], 1);
    __syncthreads();

    if (tid == 0) {
        int acc = 0;
        #pragma unroll
        for (int b = 0; b < NBKT_R; b++) { lofs[b] = acc; acc += hist[b]; }
        lofs[NBKT_R] = acc;
    }
    __syncthreads();
    if (tid < NBKT_R) {
        gofs[tid] = atomicAdd(&g_cursor[tid * KOFF + k], hist[tid]);
        wcur[tid] = lofs[tid];
    }
    __syncthreads();

    for (int i = tid; i < 8192; i += 256) {
        const int o = om[i];
        const int b = o >> RANGE_SHIFT;
        const int p = atomicAdd(&wcur[b], 1);
        stage_om[p] = o;
        stage_im[p] = im[i];
    }
    __syncthreads();

    for (int i = tid; i < 8192; i += 256) {
        int b = 0;
        #pragma unroll
        for (int bb = 1; bb < NBKT_R; bb++) b += (i >= lofs[bb]);
        const int bucket = b * KOFF + k;
        const int dst = gofs[b] + (i - lofs[b]);
        if (dst < (bucket + 1) * BKT_CAP) {          // overflow clamp
            g_im_s[dst] = stage_im[i];
            g_om_s[dst] = stage_om[i];
        }
    }
}

// ---------------------------------------------------------------------------
// Kernel 1: sparse conv over bucketed pairs. Software-pipelined fp16 gather
// -> mma m16n8k16 (f32 acc) -> smem stage -> cp.reduce.async.bulk scatter.
// All concurrent blocks share one 4 MB out-range -> RMW stays in L2.
// grid = NBUCKET * BLK_PER_BKT (range-major). Block: 8 warps, 4 tiles x 128.
// ---------------------------------------------------------------------------
__global__ void __launch_bounds__(256, 2)
conv_kernel(float* __restrict__ out)
{
    extern __shared__ char dynsmem[];
    uint32_t* WsP  = reinterpret_cast<uint32_t*>(dynsmem);
    float*    buf0 = reinterpret_cast<float*>(dynsmem + WSP_BYTES);
    float*    buf1 = buf0 + 128 * BUF_STRIDE;

    const int bucket = blockIdx.x / BLK_PER_BKT;
    const int tb     = blockIdx.x % BLK_PER_BKT;
    const int k      = bucket % KOFF;
    const int bbase  = bucket * BKT_CAP;
    int send = g_cursor[bucket];
    if (send > bbase + BKT_CAP) send = bbase + BKT_CAP;
    const int sbase  = bbase + tb * 512;
    if (sbase >= send) return;                     // fully idle block

    const int tid = threadIdx.x;

    // Copy per-lane W blocks (already packed) into padded smem.
    {
        const uint32_t* WHk = g_WH + k * 2048;
        for (int i = tid; i < 2048; i += 256)
            WsP[(i >> 6) * WSP_STRIDE + (i & 63)] = WHk[i];
    }

    const int warp = tid >> 5;
    const int lane = tid & 31;
    const int r = lane >> 2;   // 0..7
    const int a = lane & 3;    // 0..3

    const uint32_t* Bl = WsP + lane * WSP_STRIDE;
    const int base0 = sbase + warp * 16;

    // ---- Prologue: gather tile 0 (predicated on slot < send) ----
    uint32_t A0[16];
    int orow = 0, ovalid = 0;
    {
        const int s0 = base0 + r, s1 = base0 + r + 8;
        const int im0 = (s0 < send) ? g_im_s[s0] : 0;
        const int im1 = (s1 < send) ? g_im_s[s1] : 0;
        if (lane < 16) {
            const int sl = base0 + lane;
            ovalid = (sl < send);
            orow = ovalid ? g_om_s[sl] : 0;
        }
        const uint4* r0p = reinterpret_cast<const uint4*>(
            g_featsH + (size_t)im0 * 32 + (a << 3));
        const uint4* r1p = reinterpret_cast<const uint4*>(
            g_featsH + (size_t)im1 * 32 + (a << 3));
        *reinterpret_cast<uint4*>(A0)      = r0p[0];
        *reinterpret_cast<uint4*>(A0 + 4)  = r0p[1];
        *reinterpret_cast<uint4*>(A0 + 8)  = r1p[0];
        *reinterpret_cast<uint4*>(A0 + 12) = r1p[1];
    }
    __syncthreads();   // WsP ready

    #pragma unroll
    for (int t = 0; t < 4; t++) {
        // ---- Prefetch tile t+1 ----
        uint32_t An[16];
        int orow_n = 0, ovalid_n = 0;
        if (t < 3) {
            const int basen = base0 + (t + 1) * 128;
            const int s0 = basen + r, s1 = basen + r + 8;
            const int im0 = (s0 < send) ? g_im_s[s0] : 0;
            const int im1 = (s1 < send) ? g_im_s[s1] : 0;
            if (lane < 16) {
                const int sl = basen + lane;
                ovalid_n = (sl < send);
                orow_n = ovalid_n ? g_om_s[sl] : 0;
            }
            const uint4* r0p = reinterpret_cast<const uint4*>(
                g_featsH + (size_t)im0 * 32 + (a << 3));
            const uint4* r1p = reinterpret_cast<const uint4*>(
                g_featsH + (size_t)im1 * 32 + (a << 3));
            *reinterpret_cast<uint4*>(An)      = r0p[0];
            *reinterpret_cast<uint4*>(An + 4)  = r0p[1];
            *reinterpret_cast<uint4*>(An + 8)  = r1p[0];
            *reinterpret_cast<uint4*>(An + 12) = r1p[1];
        }

        // ---- MMA on tile t (f32 accumulators) ----
        float acc[8][4];
        #pragma unroll
        for (int j = 0; j < 8; j++)
            #pragma unroll
            for (int q = 0; q < 4; q++) acc[j][q] = 0.f;

        #pragma unroll
        for (int kk = 0; kk < 4; kk++) {
            uint32_t Bk[16];
            #pragma unroll
            for (int i = 0; i < 4; i++)
                *reinterpret_cast<uint4*>(Bk + 4 * i) =
                    *reinterpret_cast<const uint4*>(Bl + kk * 16 + 4 * i);

            const uint32_t a0 = A0[2 * kk];       // rows r   : cols 2a,2a+1
            const uint32_t a1 = A0[8 + 2 * kk];   // rows r+8
            const uint32_t a2 = A0[2 * kk + 1];   // rows r   : cols 2a+8,+9
            const uint32_t a3 = A0[8 + 2 * kk + 1];

            #pragma unroll
            for (int j = 0; j < 8; j++) {
                asm volatile(
                    "mma.sync.aligned.m16n8k16.row.col.f32.f16.f16.f32 "
                    "{%0,%1,%2,%3}, {%4,%5,%6,%7}, {%8,%9}, {%0,%1,%2,%3};"
                    : "+f"(acc[j][0]), "+f"(acc[j][1]),
                      "+f"(acc[j][2]), "+f"(acc[j][3])
                    : "r"(a0), "r"(a1), "r"(a2), "r"(a3),
                      "r"(Bk[2 * j]), "r"(Bk[2 * j + 1]));
            }
        }

        // ---- Epilogue: stage 16 rows, scatter via TMA bulk reduce-add ----
        float* wbuf = ((t & 1) ? buf1 : buf0) + warp * 16 * BUF_STRIDE;

        // Double buffer: the group that used THIS buffer (2 tiles ago)
        // must have finished READING its smem staging rows.
        asm volatile("cp.async.bulk.wait_group.read 1;" ::: "memory");
        __syncwarp();

        // mma D layout: lane(r,a) holds D[r, j*8+2a..+1], D[r+8, ...].
        #pragma unroll
        for (int j = 0; j < 8; j++) {
            *reinterpret_cast<float2*>(wbuf + r * BUF_STRIDE + j * 8 + 2 * a)
                = make_float2(acc[j][0], acc[j][1]);
            *reinterpret_cast<float2*>(wbuf + (r + 8) * BUF_STRIDE + j * 8 + 2 * a)
                = make_float2(acc[j][2], acc[j][3]);
        }
        __syncwarp();
        asm volatile("fence.proxy.async.shared::cta;" ::: "memory");

        if (lane < 16 && ovalid) {
            float* dst = out + (size_t)orow * COUT;
            uint32_t src = smem_u32(wbuf + lane * BUF_STRIDE);
            asm volatile(
                "cp.reduce.async.bulk.global.shared::cta.bulk_group.add.f32 "
                "[%0], [%1], %2;"
                :: "l"(dst), "r"(src), "r"(256) : "memory");
        }
        asm volatile("cp.async.bulk.commit_group;" ::: "memory");

        // rotate pipeline registers
        orow = orow_n; ovalid = ovalid_n;
        #pragma unroll
        for (int i = 0; i < 16; i++) A0[i] = An[i];
    }

    // All reduce writes must complete before kernel end.
    asm volatile("cp.async.bulk.wait_group 0;" ::: "memory");
}

// ---------------------------------------------------------------------------
// Kernel 2: per-column sum / sumsq, float4 loads.
// grid = 1024 blocks x 256 threads; 256 rows per block.
// ---------------------------------------------------------------------------
__global__ void stats_kernel(const float4* __restrict__ out4) {
    __shared__ float4 ssum[256], ssq[256];
    const int tid = threadIdx.x;
    const int c4  = tid & 15;
    const int q   = tid >> 4;
    const int rowbase = blockIdx.x * 256;

    float4 s  = make_float4(0.f, 0.f, 0.f, 0.f);
    float4 s2 = make_float4(0.f, 0.f, 0.f, 0.f);
    #pragma unroll 16
    for (int i = 0; i < 16; i++) {
        const float4 v = out4[(size_t)(rowbase + i * 16 + q) * 16 + c4];
        s.x += v.x; s.y += v.y; s.z += v.z; s.w += v.w;
        s2.x += v.x * v.x; s2.y += v.y * v.y;
        s2.z += v.z * v.z; s2.w += v.w * v.w;
    }
    ssum[tid] = s; ssq[tid] = s2;
    __syncthreads();
    if (q == 0) {
        float4 ts  = make_float4(0.f, 0.f, 0.f, 0.f);
        float4 ts2 = make_float4(0.f, 0.f, 0.f, 0.f);
        #pragma unroll
        for (int g = 0; g < 16; g++) {
            const float4 u = ssum[g * 16 + c4];
            const float4 u2 = ssq[g * 16 + c4];
            ts.x += u.x; ts.y += u.y; ts.z += u.z; ts.w += u.w;
            ts2.x += u2.x; ts2.y += u2.y; ts2.z += u2.z; ts2.w += u2.w;
        }
        atomicAdd(&g_sum[c4 * 4 + 0], ts.x);
        atomicAdd(&g_sum[c4 * 4 + 1], ts.y);
        atomicAdd(&g_sum[c4 * 4 + 2], ts.z);
        atomicAdd(&g_sum[c4 * 4 + 3], ts.w);
        atomicAdd(&g_sumsq[c4 * 4 + 0], ts2.x);
        atomicAdd(&g_sumsq[c4 * 4 + 1], ts2.y);
        atomicAdd(&g_sumsq[c4 * 4 + 2], ts2.z);
        atomicAdd(&g_sumsq[c4 * 4 + 3], ts2.w);
    }
}

// ---------------------------------------------------------------------------
// Kernel 3: BN affine + LeakyReLU, in place, float4 vectorized
// ---------------------------------------------------------------------------
__global__ void apply_kernel(float* __restrict__ out,
                             const float* __restrict__ gamma,
                             const float* __restrict__ beta)
{
    __shared__ float sc[COUT], bi[COUT];
    const int tid = threadIdx.x;
    if (tid < COUT) {
        const float inv_n = 1.f / (float)NOUT;
        float mean = g_sum[tid] * inv_n;
        float var  = g_sumsq[tid] * inv_n - mean * mean;
        float s = gamma[tid] * rsqrtf(var + EPS);
        sc[tid] = s;
        bi[tid] = beta[tid] - mean * s;
    }
    __syncthreads();

    const int idx = blockIdx.x * blockDim.x + tid;   // over 4,194,304 float4
    float4* o4 = reinterpret_cast<float4*>(out);
    float4 v = o4[idx];
    const int c = (idx & 15) * 4;
    float y0 = v.x * sc[c + 0] + bi[c + 0];
    float y1 = v.y * sc[c + 1] + bi[c + 1];
    float y2 = v.z * sc[c + 2] + bi[c + 2];
    float y3 = v.w * sc[c + 3] + bi[c + 3];
    v.x = (y0 >= 0.f) ? y0 : SLOPE * y0;
    v.y = (y1 >= 0.f) ? y1 : SLOPE * y1;
    v.z = (y2 >= 0.f) ? y2 : SLOPE * y2;
    v.w = (y3 >= 0.f) ? y3 : SLOPE * y3;
    o4[idx] = v;
}

// ---------------------------------------------------------------------------
// Launch
// inputs (metadata order): feats f32[N_IN*64], W f32[27*64*64], gamma f32[64],
//   beta f32[64], in_map i32[27*M], out_map i32[27*M], num_out i32[1]
// ---------------------------------------------------------------------------
extern "C" void kernel_launch(void* const* d_in, const int* in_sizes, int n_in,
                              void* d_out, int out_size)
{
    const float* feats   = (const float*)d_in[0];
    const float* W       = (const float*)d_in[1];
    const float* gamma   = (const float*)d_in[2];
    const float* beta    = (const float*)d_in[3];
    const int*   in_map  = (const int*)d_in[4];
    const int*   out_map = (const int*)d_in[5];
    float*       out     = (float*)d_out;

    const int n_f4 = (NOUT * COUT) / 4;          // 4,194,304

    precvt_kernel<<<8192, 256>>>(feats, W, reinterpret_cast<float4*>(out));

    cudaFuncSetAttribute(bin_kernel,
                         cudaFuncAttributeMaxDynamicSharedMemorySize,
                         BIN_SMEM);
    bin_kernel<<<dim3(16, KOFF), 256, BIN_SMEM>>>(in_map, out_map);

    cudaFuncSetAttribute(conv_kernel,
                         cudaFuncAttributeMaxDynamicSharedMemorySize,
                         SMEM_BYTES);
    conv_kernel<<<NBUCKET * BLK_PER_BKT, 256, SMEM_BYTES>>>(out);

    stats_kernel<<<1024, 256>>>(reinterpret_cast<const float4*>(out));

    apply_kernel<<<n_f4 / 256, 256>>>(out, gamma, beta);
}

// round 10
// speedup vs baseline: 1.2016x; 1.2016x over previous
#include <cuda_runtime.h>
#include <cuda_fp16.h>
#include <cstdint>

// Problem constants (fixed by the reference)
#define CIN   64
#define COUT  64
#define KOFF  27
#define MPAIR 131072
#define NOUT  262144
#define NIN   262144
#define EPS   1e-5f
#define SLOPE 0.01f

// conv tiling: block = 256 threads (8 warps); warp = 8 pairs/step;
// block = 64 pairs/step x 32 steps = 2048 pairs. grid = (64, 27).
#define BLK_PAIRS 2048
#define STEPS     32

// smem: two staging buffers of 64 rows x 68 floats (272B row stride)
#define BUF_STRIDE 68
#define BUF_ROWS   64
#define BUF_FLOATS (BUF_ROWS * BUF_STRIDE)
#define SMEM_BYTES (2 * BUF_FLOATS * 4)     // 34816

// Pre-converted fp16 operands (device scratch; no runtime allocation)
// feats row layout (32 uints = 64 fp16): uint index p = a*8 + kt*2 + h
// holds half2( feats[ci], feats[ci+1] ), ci = kt*16 + 2a + 8h.
__device__ uint32_t g_featsH[NIN * 32];          // 33.5 MB
// W fragments per k: lane-major, lane (r,a) owns 64 uints:
// index mt*16 + kt*4 + j, j bit0 = cout+8, bit1 = cin+8:
//   half2( W[ci][co], W[ci+1][co] ), ci = 16kt+2a+8*(j>>1), co = 16mt+r+8*(j&1)
__device__ uint32_t g_WH[KOFF * 2048];           // 216 KB

// BN statistics scratch
__device__ float g_sum[COUT];
__device__ float g_sumsq[COUT];

__device__ __forceinline__ uint32_t smem_u32(const void* p) {
    uint32_t a;
    asm("{ .reg .u64 t; cvta.to.shared.u64 t, %1; cvt.u32.u64 %0, t; }"
        : "=r"(a) : "l"(p));
    return a;
}

// ---------------------------------------------------------------------------
// Kernel 0: fused zero(out) + pre-convert feats/W to fp16 fragment layouts.
// grid = 8192 x 256.
// ---------------------------------------------------------------------------
__global__ void __launch_bounds__(256)
precvt_kernel(const float* __restrict__ feats, const float* __restrict__ W,
              float4* __restrict__ out4)
{
    const int tid = threadIdx.x;
    const int t4  = blockIdx.x * 256 + tid;        // 0 .. 2,097,151

    // zero the 67 MB accumulator (2 float4s per thread)
    const float4 z = make_float4(0.f, 0.f, 0.f, 0.f);
    out4[2 * (size_t)t4]     = z;
    out4[2 * (size_t)t4 + 1] = z;
    if (blockIdx.x == 0 && tid < COUT) {
        g_sum[tid]   = 0.f;
        g_sumsq[tid] = 0.f;
    }

    // feats packing (B-fragment layout)
    const int row = t4 >> 3;
    const int p0  = (t4 & 7) << 2;                 // first of 4 uint slots
    const float* src = feats + (size_t)row * CIN;
    uint32_t v[4];
    #pragma unroll
    for (int i = 0; i < 4; i++) {
        const int up = p0 + i;
        const int a  = up >> 3;
        const int kt = (up >> 1) & 3;
        const int h  = up & 1;
        const int ci = kt * 16 + 2 * a + 8 * h;
        __half2 hv = __floats2half2_rn(src[ci], src[ci + 1]);
        v[i] = *reinterpret_cast<uint32_t*>(&hv);
    }
    *reinterpret_cast<uint4*>(g_featsH + (size_t)row * 32 + p0) =
        make_uint4(v[0], v[1], v[2], v[3]);

    // W packing (A-fragment, lane-stationary layout)
    if (blockIdx.x < KOFF) {
        const float* Wk = W + blockIdx.x * (CIN * COUT);
        uint32_t* dst = g_WH + blockIdx.x * 2048;
        for (int i = tid; i < 2048; i += 256) {
            const int lane = i >> 6;
            const int rem  = i & 63;
            const int mt   = rem >> 4;
            const int kt   = (rem >> 2) & 3;
            const int j    = rem & 3;
            const int r    = lane >> 2;
            const int a    = lane & 3;
            const int ci   = 16 * kt + 2 * a + 8 * (j >> 1);
            const int co   = 16 * mt + r + 8 * (j & 1);
            __half2 hv = __floats2half2_rn(Wk[ci * COUT + co],
                                           Wk[(ci + 1) * COUT + co]);
            dst[i] = *reinterpret_cast<uint32_t*>(&hv);
        }
    }
}

// ---------------------------------------------------------------------------
// Kernel 1: sparse conv, register-stationary W (A operand), feats as B.
// D[cout=64, pair=8] per warp-step via 16x mma m16n8k16 (f32 acc).
// No LDS in the hot loop. Scatter via cp.reduce.async.bulk, double buffered.
// grid = (MPAIR/2048, KOFF); block = 256.
// ---------------------------------------------------------------------------
__global__ void __launch_bounds__(256, 2)
conv_kernel(const int* __restrict__ in_map,
            const int* __restrict__ out_map,
            float*     __restrict__ out)
{
    extern __shared__ float bufs[];

    const int k    = blockIdx.y;
    const int tid  = threadIdx.x;
    const int warp = tid >> 5;
    const int lane = tid & 31;
    const int r = lane >> 2;   // 0..7 (fragment group id)
    const int a = lane & 3;    // 0..3

    const int* im = in_map  + k * MPAIR;
    const int* om = out_map + k * MPAIR;

    // ---- stationary W fragments: 64 uints per lane, loaded once ----
    uint32_t Wf[64];
    {
        const uint4* wp = reinterpret_cast<const uint4*>(
            g_WH + k * 2048 + lane * 64);
        #pragma unroll
        for (int i = 0; i < 16; i++)
            *reinterpret_cast<uint4*>(Wf + 4 * i) = wp[i];
    }

    const int base_w = blockIdx.x * BLK_PAIRS + warp * 8;
    float* wbase = bufs + warp * 8 * BUF_STRIDE;

    // ---- prologue: gather step 0 ----
    uint32_t B0[8];
    int orow = 0;
    {
        const uint4* rp = reinterpret_cast<const uint4*>(
            g_featsH + (size_t)im[base_w + r] * 32 + a * 8);
        *reinterpret_cast<uint4*>(B0)     = rp[0];
        *reinterpret_cast<uint4*>(B0 + 4) = rp[1];
        if (lane < 8) orow = om[base_w + lane];
    }

    #pragma unroll 2
    for (int s = 0; s < STEPS; s++) {
        // ---- prefetch step s+1 ----
        uint32_t Bn[8];
        int orow_n = 0;
        if (s < STEPS - 1) {
            const int basen = base_w + (s + 1) * 64;
            if (lane < 8) orow_n = om[basen + lane];
            const uint4* rp = reinterpret_cast<const uint4*>(
                g_featsH + (size_t)im[basen + r] * 32 + a * 8);
            *reinterpret_cast<uint4*>(Bn)     = rp[0];
            *reinterpret_cast<uint4*>(Bn + 4) = rp[1];
        }

        // ---- MMA: D[64 cout, 8 pairs], K=64 ----
        float acc[4][4];
        #pragma unroll
        for (int mt = 0; mt < 4; mt++)
            #pragma unroll
            for (int q = 0; q < 4; q++) acc[mt][q] = 0.f;

        #pragma unroll
        for (int kt = 0; kt < 4; kt++) {
            const uint32_t b0 = B0[2 * kt];
            const uint32_t b1 = B0[2 * kt + 1];
            #pragma unroll
            for (int mt = 0; mt < 4; mt++) {
                const uint32_t* w = Wf + mt * 16 + kt * 4;
                asm volatile(
                    "mma.sync.aligned.m16n8k16.row.col.f32.f16.f16.f32 "
                    "{%0,%1,%2,%3}, {%4,%5,%6,%7}, {%8,%9}, {%0,%1,%2,%3};"
                    : "+f"(acc[mt][0]), "+f"(acc[mt][1]),
                      "+f"(acc[mt][2]), "+f"(acc[mt][3])
                    : "r"(w[0]), "r"(w[1]), "r"(w[2]), "r"(w[3]),
                      "r"(b0), "r"(b1));
            }
        }

        // ---- epilogue: stage 8 rows (pair-major), bulk reduce-add ----
        float* wbuf = wbase + (s & 1) * BUF_FLOATS;

        // the group that used THIS buffer (2 steps ago) must be read out
        asm volatile("cp.async.bulk.wait_group.read 1;" ::: "memory");
        __syncwarp();

        // D frag: lane(r,a), mt: c0=D[16mt+r][2a], c1=D[16mt+r][2a+1],
        //                        c2=D[16mt+r+8][2a], c3=D[16mt+r+8][2a+1]
        // staging row = pair (0..7), columns = cout
        #pragma unroll
        for (int mt = 0; mt < 4; mt++) {
            wbuf[(2 * a)     * BUF_STRIDE + 16 * mt + r]     = acc[mt][0];
            wbuf[(2 * a + 1) * BUF_STRIDE + 16 * mt + r]     = acc[mt][1];
            wbuf[(2 * a)     * BUF_STRIDE + 16 * mt + r + 8] = acc[mt][2];
            wbuf[(2 * a + 1) * BUF_STRIDE + 16 * mt + r + 8] = acc[mt][3];
        }
        __syncwarp();
        asm volatile("fence.proxy.async.shared::cta;" ::: "memory");

        if (lane < 8) {
            float* dst = out + (size_t)orow * COUT;
            uint32_t src = smem_u32(wbuf + lane * BUF_STRIDE);
            asm volatile(
                "cp.reduce.async.bulk.global.shared::cta.bulk_group.add.f32 "
                "[%0], [%1], %2;"
                :: "l"(dst), "r"(src), "r"(256) : "memory");
        }
        asm volatile("cp.async.bulk.commit_group;" ::: "memory");

        // rotate pipeline registers
        orow = orow_n;
        #pragma unroll
        for (int i = 0; i < 8; i++) B0[i] = Bn[i];
    }

    // all reduce writes must complete before kernel end
    asm volatile("cp.async.bulk.wait_group 0;" ::: "memory");
}

// ---------------------------------------------------------------------------
// Kernel 2: per-column sum / sumsq, float4 loads.
// grid = 512 blocks x 256 threads; 512 rows per block (32 per thread).
// ---------------------------------------------------------------------------
__global__ void stats_kernel(const float4* __restrict__ out4) {
    __shared__ float4 ssum[256], ssq[256];
    const int tid = threadIdx.x;
    const int c4  = tid & 15;
    const int q   = tid >> 4;
    const int rowbase = blockIdx.x * 512;

    float4 s  = make_float4(0.f, 0.f, 0.f, 0.f);
    float4 s2 = make_float4(0.f, 0.f, 0.f, 0.f);
    #pragma unroll 8
    for (int i = 0; i < 32; i++) {
        const float4 v = out4[(size_t)(rowbase + i * 16 + q) * 16 + c4];
        s.x += v.x; s.y += v.y; s.z += v.z; s.w += v.w;
        s2.x += v.x * v.x; s2.y += v.y * v.y;
        s2.z += v.z * v.z; s2.w += v.w * v.w;
    }
    ssum[tid] = s; ssq[tid] = s2;
    __syncthreads();
    if (q == 0) {
        float4 ts  = make_float4(0.f, 0.f, 0.f, 0.f);
        float4 ts2 = make_float4(0.f, 0.f, 0.f, 0.f);
        #pragma unroll
        for (int g = 0; g < 16; g++) {
            const float4 u  = ssum[g * 16 + c4];
            const float4 u2 = ssq[g * 16 + c4];
            ts.x += u.x; ts.y += u.y; ts.z += u.z; ts.w += u.w;
            ts2.x += u2.x; ts2.y += u2.y; ts2.z += u2.z; ts2.w += u2.w;
        }
        atomicAdd(&g_sum[c4 * 4 + 0], ts.x);
        atomicAdd(&g_sum[c4 * 4 + 1], ts.y);
        atomicAdd(&g_sum[c4 * 4 + 2], ts.z);
        atomicAdd(&g_sum[c4 * 4 + 3], ts.w);
        atomicAdd(&g_sumsq[c4 * 4 + 0], ts2.x);
        atomicAdd(&g_sumsq[c4 * 4 + 1], ts2.y);
        atomicAdd(&g_sumsq[c4 * 4 + 2], ts2.z);
        atomicAdd(&g_sumsq[c4 * 4 + 3], ts2.w);
    }
}

// ---------------------------------------------------------------------------
// Kernel 3: BN affine + LeakyReLU, in place, float4 vectorized
// ---------------------------------------------------------------------------
__global__ void apply_kernel(float* __restrict__ out,
                             const float* __restrict__ gamma,
                             const float* __restrict__ beta)
{
    __shared__ float sc[COUT], bi[COUT];
    const int tid = threadIdx.x;
    if (tid < COUT) {
        const float inv_n = 1.f / (float)NOUT;
        float mean = g_sum[tid] * inv_n;
        float var  = g_sumsq[tid] * inv_n - mean * mean;
        float s = gamma[tid] * rsqrtf(var + EPS);
        sc[tid] = s;
        bi[tid] = beta[tid] - mean * s;
    }
    __syncthreads();

    const int idx = blockIdx.x * blockDim.x + tid;   // over 4,194,304 float4
    float4* o4 = reinterpret_cast<float4*>(out);
    float4 v = o4[idx];
    const int c = (idx & 15) * 4;
    float y0 = v.x * sc[c + 0] + bi[c + 0];
    float y1 = v.y * sc[c + 1] + bi[c + 1];
    float y2 = v.z * sc[c + 2] + bi[c + 2];
    float y3 = v.w * sc[c + 3] + bi[c + 3];
    v.x = (y0 >= 0.f) ? y0 : SLOPE * y0;
    v.y = (y1 >= 0.f) ? y1 : SLOPE * y1;
    v.z = (y2 >= 0.f) ? y2 : SLOPE * y2;
    v.w = (y3 >= 0.f) ? y3 : SLOPE * y3;
    o4[idx] = v;
}

// ---------------------------------------------------------------------------
// Launch
// inputs (metadata order): feats f32[N_IN*64], W f32[27*64*64], gamma f32[64],
//   beta f32[64], in_map i32[27*M], out_map i32[27*M], num_out i32[1]
// ---------------------------------------------------------------------------
extern "C" void kernel_launch(void* const* d_in, const int* in_sizes, int n_in,
                              void* d_out, int out_size)
{
    const float* feats   = (const float*)d_in[0];
    const float* W       = (const float*)d_in[1];
    const float* gamma   = (const float*)d_in[2];
    const float* beta    = (const float*)d_in[3];
    const int*   in_map  = (const int*)d_in[4];
    const int*   out_map = (const int*)d_in[5];
    float*       out     = (float*)d_out;

    const int n_f4 = (NOUT * COUT) / 4;          // 4,194,304

    precvt_kernel<<<8192, 256>>>(feats, W, reinterpret_cast<float4*>(out));

    cudaFuncSetAttribute(conv_kernel,
                         cudaFuncAttributeMaxDynamicSharedMemorySize,
                         SMEM_BYTES);
    dim3 grid(MPAIR / BLK_PAIRS, KOFF);          // 64 x 27
    conv_kernel<<<grid, 256, SMEM_BYTES>>>(in_map, out_map, out);

    stats_kernel<<<512, 256>>>(reinterpret_cast<const float4*>(out));

    apply_kernel<<<n_f4 / 256, 256>>>(out, gamma, beta);
}